// round 3
// baseline (speedup 1.0000x reference)
#include <cuda_runtime.h>

#define BB 128
#define TT 256
#define KDIM 50
#define KK 2500          // K*K
#define START_TAG 48
#define END_TAG 49
#define NTHREADS 256
#define SLACK 26.0f

__device__ float g_apart[BB];   // (shiftsum + r_end) * ln2 per sequence
__device__ float g_gpart[BB];   // gold partial per sequence
__device__ int   g_count = 0;   // last-block-done counter (self-resetting)

__device__ __forceinline__ void cp16(void* dst_smem, const void* src) {
    unsigned s = (unsigned)__cvta_generic_to_shared(dst_smem);
    asm volatile("cp.async.cg.shared.global [%0], [%1], 16;\n" :: "r"(s), "l"(src));
}
__device__ __forceinline__ void cp_commit() {
    asm volatile("cp.async.commit_group;\n");
}
template <int N>
__device__ __forceinline__ void cp_wait() {
    asm volatile("cp.async.wait_group %0;\n" :: "n"(N));
}
__device__ __forceinline__ float ex2f(float x) {
    float y; asm("ex2.approx.f32 %0, %1;" : "=f"(y) : "f"(x)); return y;
}
__device__ __forceinline__ float lg2f(float x) {
    float y; asm("lg2.approx.f32 %0, %1;" : "=f"(y) : "f"(x)); return y;
}

__global__ __launch_bounds__(NTHREADS, 1)
void viterbi_fused_kernel(const float* __restrict__ scores,
                          const int* __restrict__ targets,
                          const int* __restrict__ lengths,
                          float* __restrict__ out) {
    __shared__ __align__(16) float buf[4 * KK + 128]; // 4 tile slots (raw -> exp2 in place) + OOB pad
    __shared__ float red2[4 * 64];                    // per-group GEMV partials
    __shared__ __align__(16) float wbuf[64];          // group-major weights: wbuf[g*16+i] = w[g+4i]
    __shared__ float gmax[2][2];                      // stale warp maxes of r (double buffered)
    __shared__ int   tg[TT];
    __shared__ float sred[8];
    __shared__ float sA;
    __shared__ int   sflag;
    __shared__ float sa[4], sg[4];

    const int b   = blockIdx.x;
    const int tid = threadIdx.x;
    const int g   = tid >> 6;     // j-group 0..3
    const int k   = tid & 63;     // column lane (active if < 50)
    const int len = lengths[b];
    const float* base = scores + (size_t)b * TT * KK;
    const float L = 1.4426950408889634f;   // log2(e)

    tg[tid] = targets[b * TT + tid];

    float gold = 0.f, shiftsum = 0.f, rEnd = 0.f, dprev = 0.f;

    auto issue = [&](int t) {
        if (t < len) {
            const float4* src = (const float4*)(base + (size_t)t * KK);
            float4* dst = (float4*)(buf + (t & 3) * KK);
            #pragma unroll
            for (int i = 0; i < 3; ++i) {
                int idx = tid + i * NTHREADS;
                if (idx < 625) cp16(dst + idx, src + idx);
            }
        }
        cp_commit();   // commit even if empty -> static group accounting
    };

    // in-place raw -> exp2(raw*L); each thread converts exactly the chunks it cp.async'd,
    // so a per-thread cp.async.wait is sufficient (no barrier needed before conversion).
    auto convert = [&](int t) {
        float4* p = (float4*)(buf + (t & 3) * KK);
        int tgt = tg[t], tq = tgt >> 2, tr = tgt & 3;
        #pragma unroll
        for (int i = 0; i < 3; ++i) {
            int idx = tid + i * NTHREADS;
            if (idx < 625) {
                float4 v = p[idx];
                if (idx == tq)   // gold gather from raw value before overwrite
                    gold += (tr == 0 ? v.x : tr == 1 ? v.y : tr == 2 ? v.z : v.w);
                v.x = ex2f(v.x * L); v.y = ex2f(v.y * L);
                v.z = ex2f(v.z * L); v.w = ex2f(v.w * L);
                p[idx] = v;
            }
        }
    };

    issue(0); issue(1); issue(2); issue(3);
    cp_wait<3>();
    __syncthreads();                           // tile0 raw visible to all

    // ---- prologue: r0 from START row, initial shift + weights ----
    float r0v = -3.0e38f;
    if (tid < 64) {
        if (k < KDIM) r0v = buf[START_TAG * KDIM + k] * L;
        if (tid == 0) gold += buf[tg[0]];
        if (k == END_TAG) rEnd = r0v;
        float m = r0v;
        #pragma unroll
        for (int o = 16; o > 0; o >>= 1) m = fmaxf(m, __shfl_xor_sync(0xFFFFFFFFu, m, o));
        if ((tid & 31) == 0) gmax[0][tid >> 5] = m;
        wbuf[tid] = 0.f;                       // zero unused w slots (j>=50, i>=13)
    }
    __syncthreads();                           // gmax + zeroed wbuf visible
    if (tid < 64) {
        float d1 = fmaxf(gmax[0][0], gmax[0][1]) + SLACK;
        dprev = d1;
        if (k < KDIM) wbuf[(k & 3) * 16 + (k >> 2)] = ex2f(r0v - d1);
    }
    cp_wait<2>(); if (1 < len) convert(1);
    cp_wait<1>(); if (2 < len) convert(2);

    for (int t = 1; t < len; ++t) {
        __syncthreads();                       // barA: wbuf + P[t] ready
        issue(t + 3);                          // early issue into drained slot (t-1)&3
        if (k < KDIM) {
            const float4* wv = (const float4*)(wbuf + g * 16);
            float4 wa = wv[0], wb = wv[1], wc = wv[2];
            float w12 = wbuf[g * 16 + 12];
            const float* Pg = buf + (t & 3) * KK + g * KDIM + k;  // offsets i*200
            float s0 =       wa.x * Pg[0];
            float s1 =       wa.y * Pg[200];
            s0 = __fmaf_rn(wa.z, Pg[400],  s0);
            s1 = __fmaf_rn(wa.w, Pg[600],  s1);
            s0 = __fmaf_rn(wb.x, Pg[800],  s0);
            s1 = __fmaf_rn(wb.y, Pg[1000], s1);
            s0 = __fmaf_rn(wb.z, Pg[1200], s0);
            s1 = __fmaf_rn(wb.w, Pg[1400], s1);
            s0 = __fmaf_rn(wc.x, Pg[1600], s0);
            s1 = __fmaf_rn(wc.y, Pg[1800], s1);
            s0 = __fmaf_rn(wc.z, Pg[2000], s0);
            s1 = __fmaf_rn(wc.w, Pg[2200], s1);
            s0 = __fmaf_rn(w12,  Pg[2400], s0);  // w=0 for g>=2 (j>=50); pad covers OOB read
            red2[(g << 6) + k] = s0 + s1;
        }
        __syncthreads();                       // barB: red2 ready, P[t] free
        cp_wait<1>();                          // tile t+2 raw landed (t+3 still in flight)
        if (t + 2 < len) convert(t + 2);       // off critical path, overlaps tail
        if (tid < 64) {
            float r = -3.0e38f;
            if (k < KDIM)
                r = lg2f(red2[k] + red2[64 + k] + red2[128 + k] + red2[192 + k]);
            shiftsum += dprev;                 // d consumed by THIS step's pass
            float dn = fmaxf(gmax[(t - 1) & 1][0], gmax[(t - 1) & 1][1]) + SLACK;
            if (k < KDIM) {
                wbuf[(k & 3) * 16 + (k >> 2)] = ex2f(r - dn);
                if (k == END_TAG) rEnd = r;
            }
            dprev = dn;
            float m = r;                       // stale max for step t+2 (off-path)
            #pragma unroll
            for (int o = 16; o > 0; o >>= 1) m = fmaxf(m, __shfl_xor_sync(0xFFFFFFFFu, m, o));
            if ((tid & 31) == 0) gmax[t & 1][tid >> 5] = m;
        }
    }

    __syncthreads();
    // block-reduce gold (spread across owner threads by convert())
    float gs = gold;
    #pragma unroll
    for (int o = 16; o > 0; o >>= 1) gs += __shfl_xor_sync(0xFFFFFFFFu, gs, o);
    if ((tid & 31) == 0) sred[tid >> 5] = gs;
    if (tid == END_TAG) sA = (shiftsum + rEnd) * 0.6931471805599453f;  // tid 49 = g0 lane END
    __syncthreads();
    if (tid == 0) {
        float G = sred[0] + sred[1] + sred[2] + sred[3]
                + sred[4] + sred[5] + sred[6] + sred[7];
        g_gpart[b] = G;
        g_apart[b] = sA;
        __threadfence();
        int old = atomicAdd(&g_count, 1);
        sflag = (old == BB - 1) ? 1 : 0;
    }
    __syncthreads();

    if (sflag) {                               // last block: deterministic final reduce
        __threadfence();
        float a = 0.f, gd = 0.f;
        if (tid < BB) { a = g_apart[tid]; gd = g_gpart[tid]; }
        #pragma unroll
        for (int o = 16; o > 0; o >>= 1) {
            a  += __shfl_down_sync(0xFFFFFFFFu, a, o);
            gd += __shfl_down_sync(0xFFFFFFFFu, gd, o);
        }
        if ((tid & 31) == 0) { sa[tid >> 5] = a; sg[tid >> 5] = gd; }
        __syncthreads();
        if (tid == 0) {
            float A = sa[0] + sa[1] + sa[2] + sa[3];
            float G = sg[0] + sg[1] + sg[2] + sg[3];
            out[0] = (A - G) / (float)BB;
            atomicExch(&g_count, 0);           // reset for next graph replay
        }
    }
}

extern "C" void kernel_launch(void* const* d_in, const int* in_sizes, int n_in,
                              void* d_out, int out_size) {
    const float* scores  = (const float*)d_in[0];
    const int*   targets = (const int*)d_in[1];
    const int*   lengths = (const int*)d_in[2];
    // d_in[3] = tmap_correct (unused scalar)
    viterbi_fused_kernel<<<BB, NTHREADS>>>(scores, targets, lengths, (float*)d_out);
}